// round 4
// baseline (speedup 1.0000x reference)
#include <cuda_runtime.h>
#include <cstdint>

#define N_NODES 8192
#define IN_F    512
#define OUT_F   256

#define BM 128
#define BN 128
#define BK 32
#define NTHREADS 512
#define NSTAGE 4
#define A_TILE_BYTES 16384               // 128 rows x 128B
#define STAGE_BYTES  32768               // A + B
#define SMEM_DYN     (NSTAGE * STAGE_BYTES)

__device__ float g_d [N_NODES];
__device__ float g_Wt[(size_t)OUT_F * IN_F];      // W^T, tf32-rounded, [n][k]
__device__ float g_Yt[(size_t)OUT_F * N_NODES];   // Y^T, tf32-rounded, [n][j]

__device__ __forceinline__ uint32_t smem_to_u32(const void* p) {
    uint32_t a;
    asm("{ .reg .u64 t; cvta.to.shared.u64 t, %1; cvt.u32.u64 %0, t; }" : "=r"(a) : "l"(p));
    return a;
}

#define SWZ(o) ((o) ^ (((o) >> 3) & 0x70))

#define CP_ASYNC_CG16(dst_u32, src_ptr) \
    asm volatile("cp.async.cg.shared.global [%0], [%1], 16;" :: "r"(dst_u32), "l"(src_ptr) : "memory")
#define CP_COMMIT()  asm volatile("cp.async.commit_group;" ::: "memory")
#define CP_WAIT2()   asm volatile("cp.async.wait_group 2;" ::: "memory")

#define LDSM_X4(r, addr) \
    asm volatile("ldmatrix.sync.aligned.m8n8.x4.shared.b16 {%0,%1,%2,%3}, [%4];" \
        : "=r"((r)[0]), "=r"((r)[1]), "=r"((r)[2]), "=r"((r)[3]) : "r"(addr))

#define MMA_TF32(c, a, b0, b1) \
    asm volatile("mma.sync.aligned.m16n8k8.row.col.f32.tf32.tf32.f32 " \
        "{%0,%1,%2,%3}, {%4,%5,%6,%7}, {%8,%9}, {%0,%1,%2,%3};" \
        : "+f"((c)[0]), "+f"((c)[1]), "+f"((c)[2]), "+f"((c)[3]) \
        : "r"((a)[0]), "r"((a)[1]), "r"((a)[2]), "r"((a)[3]), "r"(b0), "r"(b1))

__device__ __forceinline__ uint32_t tf32_rna(float v) {
    uint32_t t;
    asm("cvt.rna.tf32.f32 %0, %1;" : "=r"(t) : "f"(v));
    return t;
}

// ---------------------------------------------------------------------------
__global__ void rowsum_rsqrt_kernel(const float* __restrict__ A, float* __restrict__ d) {
    __shared__ float red[8];
    const int row = blockIdx.x;
    const float4* a4 = reinterpret_cast<const float4*>(A + (size_t)row * N_NODES);
    float s = 0.0f;
#pragma unroll
    for (int i = 0; i < 8; i++) {
        float4 v = __ldcs(&a4[threadIdx.x + i * 256]);
        s += (v.x + v.y) + (v.z + v.w);
    }
#pragma unroll
    for (int o = 16; o; o >>= 1) s += __shfl_xor_sync(0xffffffffu, s, o);
    if ((threadIdx.x & 31) == 0) red[threadIdx.x >> 5] = s;
    __syncthreads();
    if (threadIdx.x < 8) {
        float t = red[threadIdx.x];
#pragma unroll
        for (int o = 4; o; o >>= 1) t += __shfl_xor_sync(0xffu, t, o);
        if (threadIdx.x == 0) d[row] = rsqrtf(1.0f + t);
    }
}

// Wt[n][k] = tf32_rna(W[k][n]); W is [IN_F, OUT_F]
__global__ void transpose_round_kernel(const float* __restrict__ W, float* __restrict__ Wt) {
    __shared__ float t[32][33];
    const int n0 = blockIdx.x * 32, k0 = blockIdx.y * 32;
    const int x = threadIdx.x, y = threadIdx.y;
#pragma unroll
    for (int j = 0; j < 32; j += 8)
        t[y + j][x] = W[(size_t)(k0 + y + j) * OUT_F + n0 + x];
    __syncthreads();
#pragma unroll
    for (int j = 0; j < 32; j += 8)
        reinterpret_cast<uint32_t*>(Wt)[(size_t)(n0 + y + j) * IN_F + k0 + x] = tf32_rna(t[x][y + j]);
}

// ---------------------------------------------------------------------------
// D[m,n] = sum_k Aop[m,k]*Bop[n,k], both K-major, row pitch = K floats.
// 512 threads, 16 warps in 4(m) x 4(n), warp tile 32x32.
//   TRANS_OUT=0: Cout[m*out_ld + n] = d[m]*val (fp32)
//   TRANS_OUT=1: Cout[n*out_ld + m] = tf32_rna(d[m]*val)
template <bool TRANS_OUT>
__global__ __launch_bounds__(NTHREADS, 1)
void gemm_tf32_kernel(const float* __restrict__ Aop, const float* __restrict__ Bop,
                      float* __restrict__ Cout, const float* __restrict__ dvec,
                      int K, int out_ld) {
    extern __shared__ char smem[];
    const uint32_t sbase = smem_to_u32(smem);
    const int tid = threadIdx.x;
    const int lane = tid & 31;
    const int wid = tid >> 5;
    const int wm = wid & 3;       // 4 warps in m
    const int wn = wid >> 2;      // 4 warps in n
    const int KT = K / BK;

    // ---- cp.async plan: per-thread 2 chunks A + 2 chunks B (16B each) ----
    uint32_t sOff[2];
    size_t   gOff[2];
#pragma unroll
    for (int i = 0; i < 2; i++) {
        int chunk = i * NTHREADS + tid;     // 0..1023
        int row = chunk >> 3, c = chunk & 7;
        sOff[i] = SWZ((uint32_t)(row * 128 + c * 16));
        gOff[i] = (size_t)row * K + (size_t)c * 4;
    }
    const float* aP = Aop + (size_t)blockIdx.x * BM * K;
    const float* bP = Bop + (size_t)blockIdx.y * BN * K;

    auto load_tile = [&](int kt, int slot) {
        const uint32_t base = sbase + (uint32_t)slot * STAGE_BYTES;
        const float* a = aP + (size_t)kt * BK;
        const float* b = bP + (size_t)kt * BK;
#pragma unroll
        for (int i = 0; i < 2; i++) CP_ASYNC_CG16(base + sOff[i], a + gOff[i]);
#pragma unroll
        for (int i = 0; i < 2; i++) CP_ASYNC_CG16(base + A_TILE_BYTES + sOff[i], b + gOff[i]);
    };

    // ---- ldmatrix address precompute ----
    // A frag f (m16,k8): mats [m0-7,k0-3][m8-15,k0-3][m0-7,k4-7][m8-15,k4-7]
    uint32_t aRow[2], aX[2];
    const uint32_t aK = ((lane >> 4) & 1) * 16;
#pragma unroll
    for (int f = 0; f < 2; f++) {
        int m = wm * 32 + f * 16 + (lane & 7) + ((lane >> 3) & 1) * 8;
        aRow[f] = (uint32_t)(m * 128);
        aX[f]   = (uint32_t)((m & 7) << 4);
    }
    // B group g (n16,k8): mats [n0-7,klo][n0-7,khi][n8-15,klo][n8-15,khi]
    uint32_t bRow[2], bX[2];
    const uint32_t bK = ((lane >> 3) & 1) * 16;
#pragma unroll
    for (int g = 0; g < 2; g++) {
        int n = wn * 32 + g * 16 + ((lane >> 4) & 1) * 8 + (lane & 7);
        bRow[g] = (uint32_t)(A_TILE_BYTES + n * 128);
        bX[g]   = (uint32_t)((n & 7) << 4);
    }

    float acc[2][4][4];
#pragma unroll
    for (int i = 0; i < 2; i++)
#pragma unroll
        for (int j = 0; j < 4; j++)
#pragma unroll
            for (int r = 0; r < 4; r++) acc[i][j][r] = 0.0f;

    // ---- pipeline prologue ----
#pragma unroll
    for (int s = 0; s < NSTAGE - 1; s++) { load_tile(s, s); CP_COMMIT(); }

    // ---- main loop ----
    for (int k = 0; k < KT; k++) {
        CP_WAIT2();
        __syncthreads();
        const int kn = k + NSTAGE - 1;
        if (kn < KT) load_tile(kn, kn & (NSTAGE - 1));
        CP_COMMIT();

        const uint32_t stage = sbase + (uint32_t)(k & (NSTAGE - 1)) * STAGE_BYTES;
#pragma unroll
        for (int ks = 0; ks < 4; ks++) {
            uint32_t af[2][4], bf[2][4];
            const uint32_t kb = (uint32_t)(ks * 32);
#pragma unroll
            for (int f = 0; f < 2; f++)
                LDSM_X4(af[f], stage + aRow[f] + ((kb + aK) ^ aX[f]));
#pragma unroll
            for (int g = 0; g < 2; g++)
                LDSM_X4(bf[g], stage + bRow[g] + ((kb + bK) ^ bX[g]));
#pragma unroll
            for (int mf = 0; mf < 2; mf++)
#pragma unroll
                for (int nf = 0; nf < 4; nf++)
                    MMA_TF32(acc[mf][nf], af[mf], bf[nf >> 1][(nf & 1) * 2],
                             bf[nf >> 1][(nf & 1) * 2 + 1]);
        }
    }

    // ---- epilogue ----
    const int mBase = blockIdx.x * BM + wm * 32;
    const int nBase = blockIdx.y * BN + wn * 32;
#pragma unroll
    for (int mf = 0; mf < 2; mf++) {
        const int m0 = mBase + mf * 16 + (lane >> 2);
        const float d0 = dvec[m0];
        const float d8 = dvec[m0 + 8];
#pragma unroll
        for (int nf = 0; nf < 4; nf++) {
            const int n = nBase + nf * 8 + (lane & 3) * 2;
            if (TRANS_OUT) {
                uint32_t* C = reinterpret_cast<uint32_t*>(Cout);
                C[(size_t)n       * out_ld + m0    ] = tf32_rna(d0 * acc[mf][nf][0]);
                C[(size_t)(n + 1) * out_ld + m0    ] = tf32_rna(d0 * acc[mf][nf][1]);
                C[(size_t)n       * out_ld + m0 + 8] = tf32_rna(d8 * acc[mf][nf][2]);
                C[(size_t)(n + 1) * out_ld + m0 + 8] = tf32_rna(d8 * acc[mf][nf][3]);
            } else {
                float2 v0 = make_float2(d0 * acc[mf][nf][0], d0 * acc[mf][nf][1]);
                float2 v1 = make_float2(d8 * acc[mf][nf][2], d8 * acc[mf][nf][3]);
                *reinterpret_cast<float2*>(&Cout[(size_t)m0       * out_ld + n]) = v0;
                *reinterpret_cast<float2*>(&Cout[(size_t)(m0 + 8) * out_ld + n]) = v1;
            }
        }
    }
}

// ---------------------------------------------------------------------------
extern "C" void kernel_launch(void* const* d_in, const int* in_sizes, int n_in,
                              void* d_out, int out_size) {
    const float* A = (const float*)d_in[0];
    const float* X = (const float*)d_in[1];
    const float* W = (const float*)d_in[2];
    float* out = (float*)d_out;
    (void)in_sizes; (void)n_in; (void)out_size;

    float *dv, *Wt, *Yt;
    cudaGetSymbolAddress((void**)&dv, g_d);
    cudaGetSymbolAddress((void**)&Wt, g_Wt);
    cudaGetSymbolAddress((void**)&Yt, g_Yt);

    cudaFuncSetAttribute(gemm_tf32_kernel<true>,
                         cudaFuncAttributeMaxDynamicSharedMemorySize, SMEM_DYN);
    cudaFuncSetAttribute(gemm_tf32_kernel<false>,
                         cudaFuncAttributeMaxDynamicSharedMemorySize, SMEM_DYN);

    // d = rsqrt(1 + rowsum(A))
    rowsum_rsqrt_kernel<<<N_NODES, 256>>>(A, dv);
    // Wt[n][k] = tf32(W[k][n])
    transpose_round_kernel<<<dim3(OUT_F / 32, IN_F / 32), dim3(32, 8)>>>(W, Wt);

    // GEMM1: Yt[n][m] = tf32( d[m] * sum_k X[m][k] * Wt[n][k] )
    gemm_tf32_kernel<true><<<dim3(N_NODES / BM, OUT_F / BN), NTHREADS, SMEM_DYN>>>(
        X, Wt, Yt, dv, IN_F, N_NODES);

    // GEMM2: out[m][n] = d[m] * sum_j A[m][j] * Yt[n][j]
    gemm_tf32_kernel<false><<<dim3(N_NODES / BM, OUT_F / BN), NTHREADS, SMEM_DYN>>>(
        A, Yt, out, dv, N_NODES, OUT_F);
}

// round 5
// speedup vs baseline: 1.1056x; 1.1056x over previous
#include <cuda_runtime.h>
#include <cstdint>

#define N_NODES 8192
#define IN_F    512
#define OUT_F   256

#define BM 128
#define BN 128
#define NTHREADS 256
#define NSTAGE 3
#define SUB_BYTES    32768               // one 32-k sub-tile: A(16KB)+B(16KB)
#define A_TILE_BYTES 16384
#define STAGE_BYTES  65536               // BK=64 stage = 2 sub-tiles
#define SMEM_DYN     (NSTAGE * STAGE_BYTES)

__device__ float g_d [N_NODES];
__device__ float g_Wt[(size_t)OUT_F * IN_F];
__device__ float g_Yt[(size_t)OUT_F * N_NODES];

__device__ __forceinline__ uint32_t smem_to_u32(const void* p) {
    uint32_t a;
    asm("{ .reg .u64 t; cvta.to.shared.u64 t, %1; cvt.u32.u64 %0, t; }" : "=r"(a) : "l"(p));
    return a;
}

#define SWZ(o) ((o) ^ (((o) >> 3) & 0x70))

#define CP_ASYNC_CG16(dst_u32, src_ptr) \
    asm volatile("cp.async.cg.shared.global [%0], [%1], 16;" :: "r"(dst_u32), "l"(src_ptr) : "memory")
#define CP_COMMIT()  asm volatile("cp.async.commit_group;" ::: "memory")
#define CP_WAIT1()   asm volatile("cp.async.wait_group 1;" ::: "memory")

#define LDSM_X4(r, addr) \
    asm volatile("ldmatrix.sync.aligned.m8n8.x4.shared.b16 {%0,%1,%2,%3}, [%4];" \
        : "=r"((r)[0]), "=r"((r)[1]), "=r"((r)[2]), "=r"((r)[3]) : "r"(addr))

#define MMA_TF32(c, a, b0, b1) \
    asm volatile("mma.sync.aligned.m16n8k8.row.col.f32.tf32.tf32.f32 " \
        "{%0,%1,%2,%3}, {%4,%5,%6,%7}, {%8,%9}, {%0,%1,%2,%3};" \
        : "+f"((c)[0]), "+f"((c)[1]), "+f"((c)[2]), "+f"((c)[3]) \
        : "r"((a)[0]), "r"((a)[1]), "r"((a)[2]), "r"((a)[3]), "r"(b0), "r"(b1))

__device__ __forceinline__ uint32_t tf32_rna(float v) {
    uint32_t t;
    asm("cvt.rna.tf32.f32 %0, %1;" : "=r"(t) : "f"(v));
    return t;
}

// ---------------------------------------------------------------------------
__global__ void rowsum_rsqrt_kernel(const float* __restrict__ A, float* __restrict__ d) {
    __shared__ float red[8];
    const int row = blockIdx.x;
    const float4* a4 = reinterpret_cast<const float4*>(A + (size_t)row * N_NODES);
    float s = 0.0f;
#pragma unroll
    for (int i = 0; i < 8; i++) {
        float4 v = __ldcs(&a4[threadIdx.x + i * 256]);
        s += (v.x + v.y) + (v.z + v.w);
    }
#pragma unroll
    for (int o = 16; o; o >>= 1) s += __shfl_xor_sync(0xffffffffu, s, o);
    if ((threadIdx.x & 31) == 0) red[threadIdx.x >> 5] = s;
    __syncthreads();
    if (threadIdx.x < 8) {
        float t = red[threadIdx.x];
#pragma unroll
        for (int o = 4; o; o >>= 1) t += __shfl_xor_sync(0xffu, t, o);
        if (threadIdx.x == 0) d[row] = rsqrtf(1.0f + t);
    }
}

__global__ void transpose_round_kernel(const float* __restrict__ W, float* __restrict__ Wt) {
    __shared__ float t[32][33];
    const int n0 = blockIdx.x * 32, k0 = blockIdx.y * 32;
    const int x = threadIdx.x, y = threadIdx.y;
#pragma unroll
    for (int j = 0; j < 32; j += 8)
        t[y + j][x] = W[(size_t)(k0 + y + j) * OUT_F + n0 + x];
    __syncthreads();
#pragma unroll
    for (int j = 0; j < 32; j += 8)
        reinterpret_cast<uint32_t*>(Wt)[(size_t)(n0 + y + j) * IN_F + k0 + x] = tf32_rna(t[x][y + j]);
}

// ---------------------------------------------------------------------------
// D[m,n] = sum_k Aop[m,k]*Bop[n,k]; 256 threads, 8 warps 2(m)x4(n), warp 64x32.
// BK=64 stages (2x 32-k sub-tiles), NSTAGE=3, fragment double-buffering.
template <bool TRANS_OUT>
__global__ __launch_bounds__(NTHREADS, 1)
void gemm_tf32_kernel(const float* __restrict__ Aop, const float* __restrict__ Bop,
                      float* __restrict__ Cout, const float* __restrict__ dvec,
                      int K, int out_ld) {
    extern __shared__ char smem[];
    const uint32_t sbase = smem_to_u32(smem);
    const int tid = threadIdx.x;
    const int lane = tid & 31;
    const int wid = tid >> 5;
    const int wm = wid & 1;
    const int wn = wid >> 1;
    const int KT = K / 64;               // BK=64 steps

    // cp.async plan: 4 chunks A + 4 chunks B per thread per 32-k sub-tile
    uint32_t sOff[4];
    size_t   gOff[4];
#pragma unroll
    for (int i = 0; i < 4; i++) {
        int chunk = i * NTHREADS + tid;      // 0..1023
        int row = chunk >> 3, c = chunk & 7;
        sOff[i] = SWZ((uint32_t)(row * 128 + c * 16));
        gOff[i] = (size_t)row * K + (size_t)c * 4;
    }
    const float* aP = Aop + (size_t)blockIdx.x * BM * K;
    const float* bP = Bop + (size_t)blockIdx.y * BN * K;

    // load one BK=64 stage = sub-tiles 2*kt and 2*kt+1
    auto load_stage = [&](int kt, int slot) {
        const uint32_t base = sbase + (uint32_t)slot * STAGE_BYTES;
#pragma unroll
        for (int h = 0; h < 2; h++) {
            const float* a = aP + (size_t)(kt * 2 + h) * 32;
            const float* b = bP + (size_t)(kt * 2 + h) * 32;
            const uint32_t sub = base + (uint32_t)h * SUB_BYTES;
#pragma unroll
            for (int i = 0; i < 4; i++) CP_ASYNC_CG16(sub + sOff[i], a + gOff[i]);
#pragma unroll
            for (int i = 0; i < 4; i++) CP_ASYNC_CG16(sub + A_TILE_BYTES + sOff[i], b + gOff[i]);
        }
        CP_COMMIT();
    };

    // ldmatrix address precompute (within a 32-k sub-tile)
    uint32_t aRow[4], aX[4];
    const uint32_t aK = ((lane >> 4) & 1) * 16;
#pragma unroll
    for (int f = 0; f < 4; f++) {
        int m = wm * 64 + f * 16 + (lane & 7) + ((lane >> 3) & 1) * 8;
        aRow[f] = (uint32_t)(m * 128);
        aX[f]   = (uint32_t)((m & 7) << 4);
    }
    uint32_t bRow[2], bX[2];
    const uint32_t bK = ((lane >> 3) & 1) * 16;
#pragma unroll
    for (int g = 0; g < 2; g++) {
        int n = wn * 32 + g * 16 + ((lane >> 4) & 1) * 8 + (lane & 7);
        bRow[g] = (uint32_t)(A_TILE_BYTES + n * 128);
        bX[g]   = (uint32_t)((n & 7) << 4);
    }

    float acc[4][4][4];
#pragma unroll
    for (int i = 0; i < 4; i++)
#pragma unroll
        for (int j = 0; j < 4; j++)
#pragma unroll
            for (int r = 0; r < 4; r++) acc[i][j][r] = 0.0f;

    // prologue: 2 stages in flight
    load_stage(0, 0);
    load_stage(1, 1);

    uint32_t af[2][4][4], bf[2][2][4];

    for (int k = 0; k < KT; k++) {
        CP_WAIT1();
        __syncthreads();
        if (k + 2 < KT) load_stage(k + 2, (k + 2) % NSTAGE);

        const uint32_t stage = sbase + (uint32_t)(k % NSTAGE) * STAGE_BYTES;

        auto ldsm_ks = [&](int ks, int buf) {
            const uint32_t sub = stage + ((ks & 4) ? (uint32_t)SUB_BYTES : 0u);
            const uint32_t kb = (uint32_t)((ks & 3) * 32);
#pragma unroll
            for (int f = 0; f < 4; f++)
                LDSM_X4(af[buf][f], sub + aRow[f] + ((kb + aK) ^ aX[f]));
#pragma unroll
            for (int g = 0; g < 2; g++)
                LDSM_X4(bf[buf][g], sub + bRow[g] + ((kb + bK) ^ bX[g]));
        };

        ldsm_ks(0, 0);
#pragma unroll
        for (int ks = 0; ks < 8; ks++) {
            const int cur = ks & 1;
            if (ks < 7) ldsm_ks(ks + 1, cur ^ 1);
#pragma unroll
            for (int mf = 0; mf < 4; mf++)
#pragma unroll
                for (int nf = 0; nf < 4; nf++)
                    MMA_TF32(acc[mf][nf], af[cur][mf],
                             bf[cur][nf >> 1][(nf & 1) * 2],
                             bf[cur][nf >> 1][(nf & 1) * 2 + 1]);
        }
    }

    // epilogue
    const int mBase = blockIdx.x * BM + wm * 64;
    const int nBase = blockIdx.y * BN + wn * 32;
#pragma unroll
    for (int mf = 0; mf < 4; mf++) {
        const int m0 = mBase + mf * 16 + (lane >> 2);
        const float d0 = dvec[m0];
        const float d8 = dvec[m0 + 8];
#pragma unroll
        for (int nf = 0; nf < 4; nf++) {
            const int n = nBase + nf * 8 + (lane & 3) * 2;
            if (TRANS_OUT) {
                uint32_t* C = reinterpret_cast<uint32_t*>(Cout);
                C[(size_t)n       * out_ld + m0    ] = tf32_rna(d0 * acc[mf][nf][0]);
                C[(size_t)(n + 1) * out_ld + m0    ] = tf32_rna(d0 * acc[mf][nf][1]);
                C[(size_t)n       * out_ld + m0 + 8] = tf32_rna(d8 * acc[mf][nf][2]);
                C[(size_t)(n + 1) * out_ld + m0 + 8] = tf32_rna(d8 * acc[mf][nf][3]);
            } else {
                float2 v0 = make_float2(d0 * acc[mf][nf][0], d0 * acc[mf][nf][1]);
                float2 v1 = make_float2(d8 * acc[mf][nf][2], d8 * acc[mf][nf][3]);
                *reinterpret_cast<float2*>(&Cout[(size_t)m0       * out_ld + n]) = v0;
                *reinterpret_cast<float2*>(&Cout[(size_t)(m0 + 8) * out_ld + n]) = v1;
            }
        }
    }
}

// ---------------------------------------------------------------------------
extern "C" void kernel_launch(void* const* d_in, const int* in_sizes, int n_in,
                              void* d_out, int out_size) {
    const float* A = (const float*)d_in[0];
    const float* X = (const float*)d_in[1];
    const float* W = (const float*)d_in[2];
    float* out = (float*)d_out;
    (void)in_sizes; (void)n_in; (void)out_size;

    float *dv, *Wt, *Yt;
    cudaGetSymbolAddress((void**)&dv, g_d);
    cudaGetSymbolAddress((void**)&Wt, g_Wt);
    cudaGetSymbolAddress((void**)&Yt, g_Yt);

    cudaFuncSetAttribute(gemm_tf32_kernel<true>,
                         cudaFuncAttributeMaxDynamicSharedMemorySize, SMEM_DYN);
    cudaFuncSetAttribute(gemm_tf32_kernel<false>,
                         cudaFuncAttributeMaxDynamicSharedMemorySize, SMEM_DYN);

    rowsum_rsqrt_kernel<<<N_NODES, 256>>>(A, dv);
    transpose_round_kernel<<<dim3(OUT_F / 32, IN_F / 32), dim3(32, 8)>>>(W, Wt);

    // GEMM1: Yt[n][m] = tf32( d[m] * sum_k X[m][k] * Wt[n][k] )
    gemm_tf32_kernel<true><<<dim3(N_NODES / BM, OUT_F / BN), NTHREADS, SMEM_DYN>>>(
        X, Wt, Yt, dv, IN_F, N_NODES);

    // GEMM2: out[m][n] = d[m] * sum_j A[m][j] * Yt[n][j]
    gemm_tf32_kernel<false><<<dim3(N_NODES / BM, OUT_F / BN), NTHREADS, SMEM_DYN>>>(
        A, Yt, out, dv, N_NODES, OUT_F);
}

// round 6
// speedup vs baseline: 1.1541x; 1.0438x over previous
#include <cuda_runtime.h>
#include <cstdint>

#define N_NODES 8192
#define IN_F    512
#define OUT_F   256

#define BM 128
#define BN 64
#define BK 32
#define NTHREADS 128
#define NSTAGE 4
#define A_TILE_BYTES 16384               // 128 rows x 128B
#define B_TILE_BYTES 8192                // 64 rows x 128B
#define STAGE_BYTES  (A_TILE_BYTES + B_TILE_BYTES)
#define SMEM_DYN     (NSTAGE * STAGE_BYTES)   // 96 KB

__device__ float g_d [N_NODES];
__device__ float g_Wt[(size_t)OUT_F * IN_F];
__device__ float g_Yt[(size_t)OUT_F * N_NODES];

__device__ __forceinline__ uint32_t smem_to_u32(const void* p) {
    uint32_t a;
    asm("{ .reg .u64 t; cvta.to.shared.u64 t, %1; cvt.u32.u64 %0, t; }" : "=r"(a) : "l"(p));
    return a;
}

#define SWZ(o) ((o) ^ (((o) >> 3) & 0x70))

#define CP_ASYNC_CG16(dst_u32, src_ptr) \
    asm volatile("cp.async.cg.shared.global [%0], [%1], 16;" :: "r"(dst_u32), "l"(src_ptr) : "memory")
#define CP_COMMIT()  asm volatile("cp.async.commit_group;" ::: "memory")
#define CP_WAIT2()   asm volatile("cp.async.wait_group 2;" ::: "memory")

#define LDSM_X4(r, addr) \
    asm volatile("ldmatrix.sync.aligned.m8n8.x4.shared.b16 {%0,%1,%2,%3}, [%4];" \
        : "=r"((r)[0]), "=r"((r)[1]), "=r"((r)[2]), "=r"((r)[3]) : "r"(addr))

#define MMA_TF32(c, a, b0, b1) \
    asm volatile("mma.sync.aligned.m16n8k8.row.col.f32.tf32.tf32.f32 " \
        "{%0,%1,%2,%3}, {%4,%5,%6,%7}, {%8,%9}, {%0,%1,%2,%3};" \
        : "+f"((c)[0]), "+f"((c)[1]), "+f"((c)[2]), "+f"((c)[3]) \
        : "r"((a)[0]), "r"((a)[1]), "r"((a)[2]), "r"((a)[3]), "r"(b0), "r"(b1))

__device__ __forceinline__ uint32_t tf32_rna(float v) {
    uint32_t t;
    asm("cvt.rna.tf32.f32 %0, %1;" : "=r"(t) : "f"(v));
    return t;
}

// ---------------------------------------------------------------------------
__global__ void rowsum_rsqrt_kernel(const float* __restrict__ A, float* __restrict__ d) {
    __shared__ float red[8];
    const int row = blockIdx.x;
    const float4* a4 = reinterpret_cast<const float4*>(A + (size_t)row * N_NODES);
    float s = 0.0f;
#pragma unroll
    for (int i = 0; i < 8; i++) {
        float4 v = __ldcs(&a4[threadIdx.x + i * 256]);
        s += (v.x + v.y) + (v.z + v.w);
    }
#pragma unroll
    for (int o = 16; o; o >>= 1) s += __shfl_xor_sync(0xffffffffu, s, o);
    if ((threadIdx.x & 31) == 0) red[threadIdx.x >> 5] = s;
    __syncthreads();
    if (threadIdx.x < 8) {
        float t = red[threadIdx.x];
#pragma unroll
        for (int o = 4; o; o >>= 1) t += __shfl_xor_sync(0xffu, t, o);
        if (threadIdx.x == 0) d[row] = rsqrtf(1.0f + t);
    }
}

__global__ void transpose_round_kernel(const float* __restrict__ W, float* __restrict__ Wt) {
    __shared__ float t[32][33];
    const int n0 = blockIdx.x * 32, k0 = blockIdx.y * 32;
    const int x = threadIdx.x, y = threadIdx.y;
#pragma unroll
    for (int j = 0; j < 32; j += 8)
        t[y + j][x] = W[(size_t)(k0 + y + j) * OUT_F + n0 + x];
    __syncthreads();
#pragma unroll
    for (int j = 0; j < 32; j += 8)
        reinterpret_cast<uint32_t*>(Wt)[(size_t)(n0 + y + j) * IN_F + k0 + x] = tf32_rna(t[x][y + j]);
}

// ---------------------------------------------------------------------------
// D[m,n] = sum_k Aop[m,k]*Bop[n,k]; 128 threads, 4 warps 2(m)x2(n), warp 64x32.
// BK=32, NSTAGE=4, 96KB smem -> 2 CTAs/SM.
template <bool TRANS_OUT>
__global__ __launch_bounds__(NTHREADS, 2)
void gemm_tf32_kernel(const float* __restrict__ Aop, const float* __restrict__ Bop,
                      float* __restrict__ Cout, const float* __restrict__ dvec,
                      int K, int out_ld) {
    extern __shared__ char smem[];
    const uint32_t sbase = smem_to_u32(smem);
    const int tid = threadIdx.x;
    const int lane = tid & 31;
    const int wid = tid >> 5;
    const int wm = wid & 1;        // 2 warps in m
    const int wn = wid >> 1;       // 2 warps in n
    const int KT = K / BK;

    // cp.async plan: A = 1024 16B-chunks -> 8/thread; B = 512 -> 4/thread
    uint32_t sOffA[8]; size_t gOffA[8];
#pragma unroll
    for (int i = 0; i < 8; i++) {
        int chunk = i * NTHREADS + tid;
        int row = chunk >> 3, c = chunk & 7;
        sOffA[i] = SWZ((uint32_t)(row * 128 + c * 16));
        gOffA[i] = (size_t)row * K + (size_t)c * 4;
    }
    uint32_t sOffB[4]; size_t gOffB[4];
#pragma unroll
    for (int i = 0; i < 4; i++) {
        int chunk = i * NTHREADS + tid;
        int row = chunk >> 3, c = chunk & 7;
        sOffB[i] = SWZ((uint32_t)(row * 128 + c * 16));
        gOffB[i] = (size_t)row * K + (size_t)c * 4;
    }
    const float* aP = Aop + (size_t)blockIdx.x * BM * K;
    const float* bP = Bop + (size_t)blockIdx.y * BN * K;

    auto load_tile = [&](int kt, int slot) {
        const uint32_t base = sbase + (uint32_t)slot * STAGE_BYTES;
        const float* a = aP + (size_t)kt * BK;
        const float* b = bP + (size_t)kt * BK;
#pragma unroll
        for (int i = 0; i < 8; i++) CP_ASYNC_CG16(base + sOffA[i], a + gOffA[i]);
#pragma unroll
        for (int i = 0; i < 4; i++) CP_ASYNC_CG16(base + A_TILE_BYTES + sOffB[i], b + gOffB[i]);
        CP_COMMIT();
    };

    // ldmatrix addresses: A frag f covers m rows f*16.., warp m-offset wm*64
    uint32_t aRow[4], aX[4];
    const uint32_t aK = ((lane >> 4) & 1) * 16;
#pragma unroll
    for (int f = 0; f < 4; f++) {
        int m = wm * 64 + f * 16 + (lane & 7) + ((lane >> 3) & 1) * 8;
        aRow[f] = (uint32_t)(m * 128);
        aX[f]   = (uint32_t)((m & 7) << 4);
    }
    uint32_t bRow[2], bX[2];
    const uint32_t bK = ((lane >> 3) & 1) * 16;
#pragma unroll
    for (int g = 0; g < 2; g++) {
        int n = wn * 32 + g * 16 + ((lane >> 4) & 1) * 8 + (lane & 7);
        bRow[g] = (uint32_t)(A_TILE_BYTES + n * 128);
        bX[g]   = (uint32_t)((n & 7) << 4);
    }

    float acc[4][4][4];
#pragma unroll
    for (int i = 0; i < 4; i++)
#pragma unroll
        for (int j = 0; j < 4; j++)
#pragma unroll
            for (int r = 0; r < 4; r++) acc[i][j][r] = 0.0f;

#pragma unroll
    for (int s = 0; s < NSTAGE - 1; s++) load_tile(s, s);

    for (int k = 0; k < KT; k++) {
        CP_WAIT2();
        __syncthreads();
        const int kn = k + NSTAGE - 1;
        if (kn < KT) load_tile(kn, kn & (NSTAGE - 1));

        const uint32_t stage = sbase + (uint32_t)(k & (NSTAGE - 1)) * STAGE_BYTES;
#pragma unroll
        for (int ks = 0; ks < 4; ks++) {
            uint32_t af[4][4], bf[2][4];
            const uint32_t kb = (uint32_t)(ks * 32);
#pragma unroll
            for (int f = 0; f < 4; f++)
                LDSM_X4(af[f], stage + aRow[f] + ((kb + aK) ^ aX[f]));
#pragma unroll
            for (int g = 0; g < 2; g++)
                LDSM_X4(bf[g], stage + bRow[g] + ((kb + bK) ^ bX[g]));
#pragma unroll
            for (int mf = 0; mf < 4; mf++)
#pragma unroll
                for (int nf = 0; nf < 4; nf++)
                    MMA_TF32(acc[mf][nf], af[mf], bf[nf >> 1][(nf & 1) * 2],
                             bf[nf >> 1][(nf & 1) * 2 + 1]);
        }
    }

    // epilogue
    const int mBase = blockIdx.x * BM + wm * 64;
    const int nBase = blockIdx.y * BN + wn * 32;
#pragma unroll
    for (int mf = 0; mf < 4; mf++) {
        const int m0 = mBase + mf * 16 + (lane >> 2);
        const float d0 = dvec[m0];
        const float d8 = dvec[m0 + 8];
#pragma unroll
        for (int nf = 0; nf < 4; nf++) {
            const int n = nBase + nf * 8 + (lane & 3) * 2;
            if (TRANS_OUT) {
                uint32_t* C = reinterpret_cast<uint32_t*>(Cout);
                C[(size_t)n       * out_ld + m0    ] = tf32_rna(d0 * acc[mf][nf][0]);
                C[(size_t)(n + 1) * out_ld + m0    ] = tf32_rna(d0 * acc[mf][nf][1]);
                C[(size_t)n       * out_ld + m0 + 8] = tf32_rna(d8 * acc[mf][nf][2]);
                C[(size_t)(n + 1) * out_ld + m0 + 8] = tf32_rna(d8 * acc[mf][nf][3]);
            } else {
                float2 v0 = make_float2(d0 * acc[mf][nf][0], d0 * acc[mf][nf][1]);
                float2 v1 = make_float2(d8 * acc[mf][nf][2], d8 * acc[mf][nf][3]);
                *reinterpret_cast<float2*>(&Cout[(size_t)m0       * out_ld + n]) = v0;
                *reinterpret_cast<float2*>(&Cout[(size_t)(m0 + 8) * out_ld + n]) = v1;
            }
        }
    }
}

// ---------------------------------------------------------------------------
extern "C" void kernel_launch(void* const* d_in, const int* in_sizes, int n_in,
                              void* d_out, int out_size) {
    const float* A = (const float*)d_in[0];
    const float* X = (const float*)d_in[1];
    const float* W = (const float*)d_in[2];
    float* out = (float*)d_out;
    (void)in_sizes; (void)n_in; (void)out_size;

    float *dv, *Wt, *Yt;
    cudaGetSymbolAddress((void**)&dv, g_d);
    cudaGetSymbolAddress((void**)&Wt, g_Wt);
    cudaGetSymbolAddress((void**)&Yt, g_Yt);

    cudaFuncSetAttribute(gemm_tf32_kernel<true>,
                         cudaFuncAttributeMaxDynamicSharedMemorySize, SMEM_DYN);
    cudaFuncSetAttribute(gemm_tf32_kernel<false>,
                         cudaFuncAttributeMaxDynamicSharedMemorySize, SMEM_DYN);

    rowsum_rsqrt_kernel<<<N_NODES, 256>>>(A, dv);
    transpose_round_kernel<<<dim3(OUT_F / 32, IN_F / 32), dim3(32, 8)>>>(W, Wt);

    // GEMM1: Yt[n][m] = tf32( d[m] * sum_k X[m][k] * Wt[n][k] )
    gemm_tf32_kernel<true><<<dim3(N_NODES / BM, OUT_F / BN), NTHREADS, SMEM_DYN>>>(
        X, Wt, Yt, dv, IN_F, N_NODES);

    // GEMM2: out[m][n] = d[m] * sum_j A[m][j] * Yt[n][j]
    gemm_tf32_kernel<false><<<dim3(N_NODES / BM, OUT_F / BN), NTHREADS, SMEM_DYN>>>(
        A, Yt, out, dv, N_NODES, OUT_F);
}

// round 7
// speedup vs baseline: 1.5659x; 1.3569x over previous
#include <cuda_runtime.h>
#include <cuda_fp16.h>
#include <cstdint>

#define N_NODES 8192
#define IN_F    512
#define OUT_F   256

#define BM 128
#define BN 64
#define BKE 64                           // k elems per stage (fp16): 128B rows
#define NTHREADS 128
#define NSTAGE 4
#define A_TILE_BYTES 16384               // 128 rows x 128B
#define B_TILE_BYTES 8192                // 64 rows x 128B
#define STAGE_BYTES  (A_TILE_BYTES + B_TILE_BYTES)   // 24KB
#define SMEM_DYN     (NSTAGE * STAGE_BYTES)          // 96KB -> 2 CTAs/SM

__device__ float  g_d  [N_NODES];
__device__ __half g_Ah [(size_t)N_NODES * N_NODES];   // A in fp16 (rn)
__device__ __half g_Xh [(size_t)N_NODES * IN_F];
__device__ __half g_Wth[(size_t)OUT_F * IN_F];        // W^T fp16
__device__ __half g_Yth[(size_t)OUT_F * N_NODES];     // Y^T fp16

__device__ __forceinline__ uint32_t smem_to_u32(const void* p) {
    uint32_t a;
    asm("{ .reg .u64 t; cvta.to.shared.u64 t, %1; cvt.u32.u64 %0, t; }" : "=r"(a) : "l"(p));
    return a;
}

#define SWZ(o) ((o) ^ (((o) >> 3) & 0x70))

#define CP_ASYNC_CG16(dst_u32, src_ptr) \
    asm volatile("cp.async.cg.shared.global [%0], [%1], 16;" :: "r"(dst_u32), "l"(src_ptr) : "memory")
#define CP_COMMIT()  asm volatile("cp.async.commit_group;" ::: "memory")
#define CP_WAIT2()   asm volatile("cp.async.wait_group 2;" ::: "memory")

#define LDSM_X4(r, addr) \
    asm volatile("ldmatrix.sync.aligned.m8n8.x4.shared.b16 {%0,%1,%2,%3}, [%4];" \
        : "=r"((r)[0]), "=r"((r)[1]), "=r"((r)[2]), "=r"((r)[3]) : "r"(addr))

#define MMA_F16(c, a, b0, b1) \
    asm volatile("mma.sync.aligned.m16n8k16.row.col.f32.f16.f16.f32 " \
        "{%0,%1,%2,%3}, {%4,%5,%6,%7}, {%8,%9}, {%0,%1,%2,%3};" \
        : "+f"((c)[0]), "+f"((c)[1]), "+f"((c)[2]), "+f"((c)[3]) \
        : "r"((a)[0]), "r"((a)[1]), "r"((a)[2]), "r"((a)[3]), "r"(b0), "r"(b1))

// ---------------------------------------------------------------------------
// d[row] = rsqrt(1+rowsum); also writes A in fp16 (rn, unbiased).
__global__ void rowsum_rsqrt_cvt_kernel(const float* __restrict__ A,
                                        float* __restrict__ d,
                                        __half* __restrict__ Ah) {
    __shared__ float red[8];
    const int row = blockIdx.x;
    const float4* a4 = reinterpret_cast<const float4*>(A + (size_t)row * N_NODES);
    uint2* o8 = reinterpret_cast<uint2*>(Ah + (size_t)row * N_NODES);
    float s = 0.0f;
#pragma unroll
    for (int i = 0; i < 8; i++) {
        float4 v = __ldcs(&a4[threadIdx.x + i * 256]);
        s += (v.x + v.y) + (v.z + v.w);
        __half2 h0 = __floats2half2_rn(v.x, v.y);
        __half2 h1 = __floats2half2_rn(v.z, v.w);
        uint2 u;
        u.x = reinterpret_cast<uint32_t&>(h0);
        u.y = reinterpret_cast<uint32_t&>(h1);
        o8[threadIdx.x + i * 256] = u;
    }
#pragma unroll
    for (int o = 16; o; o >>= 1) s += __shfl_xor_sync(0xffffffffu, s, o);
    if ((threadIdx.x & 31) == 0) red[threadIdx.x >> 5] = s;
    __syncthreads();
    if (threadIdx.x < 8) {
        float t = red[threadIdx.x];
#pragma unroll
        for (int o = 4; o; o >>= 1) t += __shfl_xor_sync(0xffu, t, o);
        if (threadIdx.x == 0) d[row] = rsqrtf(1.0f + t);
    }
}

__global__ void cvt_x_kernel(const float* __restrict__ X, __half* __restrict__ Xh) {
    const size_t i = (size_t)blockIdx.x * blockDim.x + threadIdx.x;
    float4 v = reinterpret_cast<const float4*>(X)[i];
    __half2 h0 = __floats2half2_rn(v.x, v.y);
    __half2 h1 = __floats2half2_rn(v.z, v.w);
    uint2 u;
    u.x = reinterpret_cast<uint32_t&>(h0);
    u.y = reinterpret_cast<uint32_t&>(h1);
    reinterpret_cast<uint2*>(Xh)[i] = u;
}

// Wth[n][k] = half(W[k][n]); W is [IN_F, OUT_F]
__global__ void transpose_cvt_w_kernel(const float* __restrict__ W, __half* __restrict__ Wt) {
    __shared__ float t[32][33];
    const int n0 = blockIdx.x * 32, k0 = blockIdx.y * 32;
    const int x = threadIdx.x, y = threadIdx.y;
#pragma unroll
    for (int j = 0; j < 32; j += 8)
        t[y + j][x] = W[(size_t)(k0 + y + j) * OUT_F + n0 + x];
    __syncthreads();
#pragma unroll
    for (int j = 0; j < 32; j += 8)
        Wt[(size_t)(n0 + y + j) * IN_F + k0 + x] = __float2half_rn(t[x][y + j]);
}

// ---------------------------------------------------------------------------
// D[m,n] = sum_k Aop[m,k]*Bop[n,k], fp16 operands (K-major, pitch K elems),
// fp32 accumulate. 128 threads, 4 warps 2(m)x2(n), warp 64x32.
// BK=64 fp16 per stage (128B rows, SW128), NSTAGE=4, 2 CTAs/SM.
//   TRANS_OUT=0: ((float*)Cout)[m*out_ld + n] = d[m]*acc
//   TRANS_OUT=1: ((half*) Cout)[n*out_ld + m] = half(d[m]*acc)
template <bool TRANS_OUT>
__global__ __launch_bounds__(NTHREADS, 2)
void gemm_f16_kernel(const __half* __restrict__ Aop, const __half* __restrict__ Bop,
                     void* __restrict__ Cout, const float* __restrict__ dvec,
                     int K, int out_ld) {
    extern __shared__ char smem[];
    const uint32_t sbase = smem_to_u32(smem);
    const int tid = threadIdx.x;
    const int lane = tid & 31;
    const int wid = tid >> 5;
    const int wm = wid & 1;
    const int wn = wid >> 1;
    const int KT = K / BKE;

    // cp.async: A = 1024 16B-chunks -> 8/thread; B = 512 -> 4/thread
    uint32_t sOffA[8]; size_t gOffA[8];
#pragma unroll
    for (int i = 0; i < 8; i++) {
        int chunk = i * NTHREADS + tid;
        int row = chunk >> 3, c = chunk & 7;
        sOffA[i] = SWZ((uint32_t)(row * 128 + c * 16));
        gOffA[i] = (size_t)row * K + (size_t)c * 8;     // 16B = 8 halves
    }
    uint32_t sOffB[4]; size_t gOffB[4];
#pragma unroll
    for (int i = 0; i < 4; i++) {
        int chunk = i * NTHREADS + tid;
        int row = chunk >> 3, c = chunk & 7;
        sOffB[i] = SWZ((uint32_t)(row * 128 + c * 16));
        gOffB[i] = (size_t)row * K + (size_t)c * 8;
    }
    const __half* aP = Aop + (size_t)blockIdx.x * BM * K;
    const __half* bP = Bop + (size_t)blockIdx.y * BN * K;

    auto load_tile = [&](int kt, int slot) {
        const uint32_t base = sbase + (uint32_t)slot * STAGE_BYTES;
        const __half* a = aP + (size_t)kt * BKE;
        const __half* b = bP + (size_t)kt * BKE;
#pragma unroll
        for (int i = 0; i < 8; i++) CP_ASYNC_CG16(base + sOffA[i], a + gOffA[i]);
#pragma unroll
        for (int i = 0; i < 4; i++) CP_ASYNC_CG16(base + A_TILE_BYTES + sOffB[i], b + gOffB[i]);
        CP_COMMIT();
    };

    // ldmatrix addresses (16B = k8 halves; one x4 covers k16)
    uint32_t aRow[4], aX[4];
    const uint32_t aK = ((lane >> 4) & 1) * 16;
#pragma unroll
    for (int f = 0; f < 4; f++) {
        int m = wm * 64 + f * 16 + (lane & 7) + ((lane >> 3) & 1) * 8;
        aRow[f] = (uint32_t)(m * 128);
        aX[f]   = (uint32_t)((m & 7) << 4);
    }
    uint32_t bRow[2], bX[2];
    const uint32_t bK = ((lane >> 3) & 1) * 16;
#pragma unroll
    for (int g = 0; g < 2; g++) {
        int n = wn * 32 + g * 16 + ((lane >> 4) & 1) * 8 + (lane & 7);
        bRow[g] = (uint32_t)(A_TILE_BYTES + n * 128);
        bX[g]   = (uint32_t)((n & 7) << 4);
    }

    float acc[4][4][4];
#pragma unroll
    for (int i = 0; i < 4; i++)
#pragma unroll
        for (int j = 0; j < 4; j++)
#pragma unroll
            for (int r = 0; r < 4; r++) acc[i][j][r] = 0.0f;

#pragma unroll
    for (int s = 0; s < NSTAGE - 1; s++) load_tile(s, s);

    for (int k = 0; k < KT; k++) {
        CP_WAIT2();
        __syncthreads();
        const int kn = k + NSTAGE - 1;
        if (kn < KT) load_tile(kn, kn & (NSTAGE - 1));

        const uint32_t stage = sbase + (uint32_t)(k & (NSTAGE - 1)) * STAGE_BYTES;
#pragma unroll
        for (int ks = 0; ks < 4; ks++) {               // 4 x k16 per stage
            uint32_t af[4][4], bf[2][4];
            const uint32_t kb = (uint32_t)(ks * 32);   // 16 halves = 32B
#pragma unroll
            for (int f = 0; f < 4; f++)
                LDSM_X4(af[f], stage + aRow[f] + ((kb + aK) ^ aX[f]));
#pragma unroll
            for (int g = 0; g < 2; g++)
                LDSM_X4(bf[g], stage + bRow[g] + ((kb + bK) ^ bX[g]));
#pragma unroll
            for (int mf = 0; mf < 4; mf++)
#pragma unroll
                for (int nf = 0; nf < 4; nf++)
                    MMA_F16(acc[mf][nf], af[mf], bf[nf >> 1][(nf & 1) * 2],
                            bf[nf >> 1][(nf & 1) * 2 + 1]);
        }
    }

    // epilogue
    const int mBase = blockIdx.x * BM + wm * 64;
    const int nBase = blockIdx.y * BN + wn * 32;
#pragma unroll
    for (int mf = 0; mf < 4; mf++) {
        const int m0 = mBase + mf * 16 + (lane >> 2);
        const float d0 = dvec[m0];
        const float d8 = dvec[m0 + 8];
#pragma unroll
        for (int nf = 0; nf < 4; nf++) {
            const int n = nBase + nf * 8 + (lane & 3) * 2;
            if (TRANS_OUT) {
                __half* C = reinterpret_cast<__half*>(Cout);
                C[(size_t)n       * out_ld + m0    ] = __float2half_rn(d0 * acc[mf][nf][0]);
                C[(size_t)(n + 1) * out_ld + m0    ] = __float2half_rn(d0 * acc[mf][nf][1]);
                C[(size_t)n       * out_ld + m0 + 8] = __float2half_rn(d8 * acc[mf][nf][2]);
                C[(size_t)(n + 1) * out_ld + m0 + 8] = __float2half_rn(d8 * acc[mf][nf][3]);
            } else {
                float* C = reinterpret_cast<float*>(Cout);
                float2 v0 = make_float2(d0 * acc[mf][nf][0], d0 * acc[mf][nf][1]);
                float2 v1 = make_float2(d8 * acc[mf][nf][2], d8 * acc[mf][nf][3]);
                *reinterpret_cast<float2*>(&C[(size_t)m0       * out_ld + n]) = v0;
                *reinterpret_cast<float2*>(&C[(size_t)(m0 + 8) * out_ld + n]) = v1;
            }
        }
    }
}

// ---------------------------------------------------------------------------
extern "C" void kernel_launch(void* const* d_in, const int* in_sizes, int n_in,
                              void* d_out, int out_size) {
    const float* A = (const float*)d_in[0];
    const float* X = (const float*)d_in[1];
    const float* W = (const float*)d_in[2];
    float* out = (float*)d_out;
    (void)in_sizes; (void)n_in; (void)out_size;

    float *dv;
    __half *Ah, *Xh, *Wth, *Yth;
    cudaGetSymbolAddress((void**)&dv,  g_d);
    cudaGetSymbolAddress((void**)&Ah,  g_Ah);
    cudaGetSymbolAddress((void**)&Xh,  g_Xh);
    cudaGetSymbolAddress((void**)&Wth, g_Wth);
    cudaGetSymbolAddress((void**)&Yth, g_Yth);

    cudaFuncSetAttribute(gemm_f16_kernel<true>,
                         cudaFuncAttributeMaxDynamicSharedMemorySize, SMEM_DYN);
    cudaFuncSetAttribute(gemm_f16_kernel<false>,
                         cudaFuncAttributeMaxDynamicSharedMemorySize, SMEM_DYN);

    // d = rsqrt(1+rowsum(A)); Ah = fp16(A)
    rowsum_rsqrt_cvt_kernel<<<N_NODES, 256>>>(A, dv, Ah);
    // Xh = fp16(X)
    cvt_x_kernel<<<(N_NODES * IN_F) / (256 * 4), 256>>>(X, Xh);
    // Wth[n][k] = fp16(W[k][n])
    transpose_cvt_w_kernel<<<dim3(OUT_F / 32, IN_F / 32), dim3(32, 8)>>>(W, Wth);

    // GEMM1: Yth[n][m] = fp16( d[m] * sum_k Xh[m][k] * Wth[n][k] )
    gemm_f16_kernel<true><<<dim3(N_NODES / BM, OUT_F / BN), NTHREADS, SMEM_DYN>>>(
        Xh, Wth, (void*)Yth, dv, IN_F, N_NODES);

    // GEMM2: out[m][n] = d[m] * sum_j Ah[m][j] * Yth[n][j]
    gemm_f16_kernel<false><<<dim3(N_NODES / BM, OUT_F / BN), NTHREADS, SMEM_DYN>>>(
        Ah, Yth, (void*)out, dv, N_NODES, OUT_F);
}

// round 8
// speedup vs baseline: 1.5738x; 1.0051x over previous
#include <cuda_runtime.h>
#include <cuda_fp16.h>
#include <cstdint>

#define N_NODES 8192
#define IN_F    512
#define OUT_F   256

#define BM 64
#define BN 128
#define BKE 64                            // k halves per stage (128B rows)
#define NTHREADS 128
#define NSTAGE 4
#define A_TILE_BYTES 8192                 // 64 rows x 128B
#define B_TILE_BYTES 16384                // 128 rows x 128B
#define STAGE_BYTES  (A_TILE_BYTES + B_TILE_BYTES)   // 24KB
#define SMEM_DYN     (NSTAGE * STAGE_BYTES)          // 96KB -> 2 CTAs/SM

__device__ float  g_d  [N_NODES];
__device__ __half g_Ah [(size_t)N_NODES * N_NODES];
__device__ __half g_Xh [(size_t)N_NODES * IN_F];
__device__ __half g_Wth[(size_t)OUT_F * IN_F];
__device__ __half g_Yth[(size_t)OUT_F * N_NODES];

__device__ __forceinline__ uint32_t smem_to_u32(const void* p) {
    uint32_t a;
    asm("{ .reg .u64 t; cvta.to.shared.u64 t, %1; cvt.u32.u64 %0, t; }" : "=r"(a) : "l"(p));
    return a;
}

#define SWZ(o) ((o) ^ (((o) >> 3) & 0x70))

#define CP_ASYNC_CG16(dst_u32, src_ptr) \
    asm volatile("cp.async.cg.shared.global [%0], [%1], 16;" :: "r"(dst_u32), "l"(src_ptr) : "memory")
#define CP_COMMIT()  asm volatile("cp.async.commit_group;" ::: "memory")
#define CP_WAIT2()   asm volatile("cp.async.wait_group 2;" ::: "memory")

#define LDSM_X4(r, addr) \
    asm volatile("ldmatrix.sync.aligned.m8n8.x4.shared.b16 {%0,%1,%2,%3}, [%4];" \
        : "=r"((r)[0]), "=r"((r)[1]), "=r"((r)[2]), "=r"((r)[3]) : "r"(addr))

#define MMA_F16(c, a, b0, b1) \
    asm volatile("mma.sync.aligned.m16n8k16.row.col.f32.f16.f16.f32 " \
        "{%0,%1,%2,%3}, {%4,%5,%6,%7}, {%8,%9}, {%0,%1,%2,%3};" \
        : "+f"((c)[0]), "+f"((c)[1]), "+f"((c)[2]), "+f"((c)[3]) \
        : "r"((a)[0]), "r"((a)[1]), "r"((a)[2]), "r"((a)[3]), "r"(b0), "r"(b1))

// ---------------------------------------------------------------------------
__global__ void rowsum_rsqrt_cvt_kernel(const float* __restrict__ A,
                                        float* __restrict__ d,
                                        __half* __restrict__ Ah) {
    __shared__ float red[8];
    const int row = blockIdx.x;
    const float4* a4 = reinterpret_cast<const float4*>(A + (size_t)row * N_NODES);
    uint2* o8 = reinterpret_cast<uint2*>(Ah + (size_t)row * N_NODES);
    float s = 0.0f;
#pragma unroll
    for (int i = 0; i < 8; i++) {
        float4 v = __ldcs(&a4[threadIdx.x + i * 256]);
        s += (v.x + v.y) + (v.z + v.w);
        __half2 h0 = __floats2half2_rn(v.x, v.y);
        __half2 h1 = __floats2half2_rn(v.z, v.w);
        uint2 u;
        u.x = reinterpret_cast<uint32_t&>(h0);
        u.y = reinterpret_cast<uint32_t&>(h1);
        o8[threadIdx.x + i * 256] = u;
    }
#pragma unroll
    for (int o = 16; o; o >>= 1) s += __shfl_xor_sync(0xffffffffu, s, o);
    if ((threadIdx.x & 31) == 0) red[threadIdx.x >> 5] = s;
    __syncthreads();
    if (threadIdx.x < 8) {
        float t = red[threadIdx.x];
#pragma unroll
        for (int o = 4; o; o >>= 1) t += __shfl_xor_sync(0xffu, t, o);
        if (threadIdx.x == 0) d[row] = rsqrtf(1.0f + t);
    }
}

__global__ void cvt_x_kernel(const float* __restrict__ X, __half* __restrict__ Xh) {
    const size_t i = (size_t)blockIdx.x * blockDim.x + threadIdx.x;
    float4 v = reinterpret_cast<const float4*>(X)[i];
    __half2 h0 = __floats2half2_rn(v.x, v.y);
    __half2 h1 = __floats2half2_rn(v.z, v.w);
    uint2 u;
    u.x = reinterpret_cast<uint32_t&>(h0);
    u.y = reinterpret_cast<uint32_t&>(h1);
    reinterpret_cast<uint2*>(Xh)[i] = u;
}

__global__ void transpose_cvt_w_kernel(const float* __restrict__ W, __half* __restrict__ Wt) {
    __shared__ float t[32][33];
    const int n0 = blockIdx.x * 32, k0 = blockIdx.y * 32;
    const int x = threadIdx.x, y = threadIdx.y;
#pragma unroll
    for (int j = 0; j < 32; j += 8)
        t[y + j][x] = W[(size_t)(k0 + y + j) * OUT_F + n0 + x];
    __syncthreads();
#pragma unroll
    for (int j = 0; j < 32; j += 8)
        Wt[(size_t)(n0 + y + j) * IN_F + k0 + x] = __float2half_rn(t[x][y + j]);
}

// ---------------------------------------------------------------------------
// D[m,n] = sum_k Aop[m,k]*Bop[n,k], fp16 ops, fp32 acc.
// CTA 64x128, 128 threads, 4 warps 1(m)x4(n), warp tile 64x32.
//   TRANS_OUT=0: ((float*)Cout)[m*out_ld + n] = d[m]*acc
//   TRANS_OUT=1: ((half*) Cout)[n*out_ld + m] = half(d[m]*acc)
template <bool TRANS_OUT>
__global__ __launch_bounds__(NTHREADS, 2)
void gemm_f16_kernel(const __half* __restrict__ Aop, const __half* __restrict__ Bop,
                     void* __restrict__ Cout, const float* __restrict__ dvec,
                     int K, int out_ld) {
    extern __shared__ char smem[];
    const uint32_t sbase = smem_to_u32(smem);
    const int tid = threadIdx.x;
    const int lane = tid & 31;
    const int wn = tid >> 5;       // 4 warps in n
    const int KT = K / BKE;

    // cp.async: A = 512 16B-chunks -> 4/thread; B = 1024 -> 8/thread
    uint32_t sOffA[4]; size_t gOffA[4];
#pragma unroll
    for (int i = 0; i < 4; i++) {
        int chunk = i * NTHREADS + tid;
        int row = chunk >> 3, c = chunk & 7;
        sOffA[i] = SWZ((uint32_t)(row * 128 + c * 16));
        gOffA[i] = (size_t)row * K + (size_t)c * 8;
    }
    uint32_t sOffB[8]; size_t gOffB[8];
#pragma unroll
    for (int i = 0; i < 8; i++) {
        int chunk = i * NTHREADS + tid;
        int row = chunk >> 3, c = chunk & 7;
        sOffB[i] = SWZ((uint32_t)(row * 128 + c * 16));
        gOffB[i] = (size_t)row * K + (size_t)c * 8;
    }
    const __half* aP = Aop + (size_t)blockIdx.x * BM * K;
    const __half* bP = Bop + (size_t)blockIdx.y * BN * K;

    auto load_tile = [&](int kt, int slot) {
        const uint32_t base = sbase + (uint32_t)slot * STAGE_BYTES;
        const __half* a = aP + (size_t)kt * BKE;
        const __half* b = bP + (size_t)kt * BKE;
#pragma unroll
        for (int i = 0; i < 4; i++) CP_ASYNC_CG16(base + sOffA[i], a + gOffA[i]);
#pragma unroll
        for (int i = 0; i < 8; i++) CP_ASYNC_CG16(base + A_TILE_BYTES + sOffB[i], b + gOffB[i]);
        CP_COMMIT();
    };

    // ldmatrix addresses
    uint32_t aRow[4], aX[4];
    const uint32_t aK = ((lane >> 4) & 1) * 16;
#pragma unroll
    for (int f = 0; f < 4; f++) {
        int m = f * 16 + (lane & 7) + ((lane >> 3) & 1) * 8;   // BM=64, 1 m-warp
        aRow[f] = (uint32_t)(m * 128);
        aX[f]   = (uint32_t)((m & 7) << 4);
    }
    uint32_t bRow[2], bX[2];
    const uint32_t bK = ((lane >> 3) & 1) * 16;
#pragma unroll
    for (int g = 0; g < 2; g++) {
        int n = wn * 32 + g * 16 + ((lane >> 4) & 1) * 8 + (lane & 7);
        bRow[g] = (uint32_t)(A_TILE_BYTES + n * 128);
        bX[g]   = (uint32_t)((n & 7) << 4);
    }

    float acc[4][4][4];
#pragma unroll
    for (int i = 0; i < 4; i++)
#pragma unroll
        for (int j = 0; j < 4; j++)
#pragma unroll
            for (int r = 0; r < 4; r++) acc[i][j][r] = 0.0f;

#pragma unroll
    for (int s = 0; s < NSTAGE - 1; s++) load_tile(s, s);

    for (int k = 0; k < KT; k++) {
        CP_WAIT2();
        __syncthreads();
        const int kn = k + NSTAGE - 1;
        if (kn < KT) load_tile(kn, kn & (NSTAGE - 1));

        const uint32_t stage = sbase + (uint32_t)(k & (NSTAGE - 1)) * STAGE_BYTES;
#pragma unroll
        for (int ks = 0; ks < 4; ks++) {               // 4 x k16 per stage
            uint32_t af[4][4], bf[2][4];
            const uint32_t kb = (uint32_t)(ks * 32);   // 16 halves = 32B
#pragma unroll
            for (int f = 0; f < 4; f++)
                LDSM_X4(af[f], stage + aRow[f] + ((kb + aK) ^ aX[f]));
#pragma unroll
            for (int g = 0; g < 2; g++)
                LDSM_X4(bf[g], stage + bRow[g] + ((kb + bK) ^ bX[g]));
#pragma unroll
            for (int mf = 0; mf < 4; mf++)
#pragma unroll
                for (int nf = 0; nf < 4; nf++)
                    MMA_F16(acc[mf][nf], af[mf], bf[nf >> 1][(nf & 1) * 2],
                            bf[nf >> 1][(nf & 1) * 2 + 1]);
        }
    }

    // epilogue
    const int mBase = blockIdx.x * BM;
    const int nBase = blockIdx.y * BN + wn * 32;
#pragma unroll
    for (int mf = 0; mf < 4; mf++) {
        const int m0 = mBase + mf * 16 + (lane >> 2);
        const float d0 = dvec[m0];
        const float d8 = dvec[m0 + 8];
#pragma unroll
        for (int nf = 0; nf < 4; nf++) {
            const int n = nBase + nf * 8 + (lane & 3) * 2;
            if (TRANS_OUT) {
                __half* C = reinterpret_cast<__half*>(Cout);
                C[(size_t)n       * out_ld + m0    ] = __float2half_rn(d0 * acc[mf][nf][0]);
                C[(size_t)(n + 1) * out_ld + m0    ] = __float2half_rn(d0 * acc[mf][nf][1]);
                C[(size_t)n       * out_ld + m0 + 8] = __float2half_rn(d8 * acc[mf][nf][2]);
                C[(size_t)(n + 1) * out_ld + m0 + 8] = __float2half_rn(d8 * acc[mf][nf][3]);
            } else {
                float* C = reinterpret_cast<float*>(Cout);
                float2 v0 = make_float2(d0 * acc[mf][nf][0], d0 * acc[mf][nf][1]);
                float2 v1 = make_float2(d8 * acc[mf][nf][2], d8 * acc[mf][nf][3]);
                *reinterpret_cast<float2*>(&C[(size_t)m0       * out_ld + n]) = v0;
                *reinterpret_cast<float2*>(&C[(size_t)(m0 + 8) * out_ld + n]) = v1;
            }
        }
    }
}

// ---------------------------------------------------------------------------
extern "C" void kernel_launch(void* const* d_in, const int* in_sizes, int n_in,
                              void* d_out, int out_size) {
    const float* A = (const float*)d_in[0];
    const float* X = (const float*)d_in[1];
    const float* W = (const float*)d_in[2];
    float* out = (float*)d_out;
    (void)in_sizes; (void)n_in; (void)out_size;

    float *dv;
    __half *Ah, *Xh, *Wth, *Yth;
    cudaGetSymbolAddress((void**)&dv,  g_d);
    cudaGetSymbolAddress((void**)&Ah,  g_Ah);
    cudaGetSymbolAddress((void**)&Xh,  g_Xh);
    cudaGetSymbolAddress((void**)&Wth, g_Wth);
    cudaGetSymbolAddress((void**)&Yth, g_Yth);

    cudaFuncSetAttribute(gemm_f16_kernel<true>,
                         cudaFuncAttributeMaxDynamicSharedMemorySize, SMEM_DYN);
    cudaFuncSetAttribute(gemm_f16_kernel<false>,
                         cudaFuncAttributeMaxDynamicSharedMemorySize, SMEM_DYN);

    rowsum_rsqrt_cvt_kernel<<<N_NODES, 256>>>(A, dv, Ah);
    cvt_x_kernel<<<(N_NODES * IN_F) / (256 * 4), 256>>>(X, Xh);
    transpose_cvt_w_kernel<<<dim3(OUT_F / 32, IN_F / 32), dim3(32, 8)>>>(W, Wth);

    // GEMM1: Yth[n][m] = fp16( d[m] * sum_k Xh[m][k] * Wth[n][k] )
    gemm_f16_kernel<true><<<dim3(N_NODES / BM, OUT_F / BN), NTHREADS, SMEM_DYN>>>(
        Xh, Wth, (void*)Yth, dv, IN_F, N_NODES);

    // GEMM2: out[m][n] = d[m] * sum_j Ah[m][j] * Yth[n][j]
    gemm_f16_kernel<false><<<dim3(N_NODES / BM, OUT_F / BN), NTHREADS, SMEM_DYN>>>(
        Ah, Yth, (void*)out, dv, N_NODES, OUT_F);
}